// round 4
// baseline (speedup 1.0000x reference)
#include <cuda_runtime.h>
#include <cstdint>

// Problem shape (fixed by the dataset)
#define PK 4
#define PB 4096
#define PT 32
#define PD 128

// Output layout: pos_dist | neg_dist | pair_mask | nbr_embed, all float32,
// flattened in reference-return order.
#define PAIR_ELEMS ((size_t)PK * PB * PT * PT)   // 16,777,216
#define NBR_ELEMS  ((size_t)PK * PB * PT * PD)   // 16,777,216

__global__ __launch_bounds__(128) void distance_layer_kernel(
    const float* __restrict__ semb,     // [K,B,D]
    const int*   __restrict__ slabels,  // [K,B]
    const int*   __restrict__ topk,     // [K,B,T]
    float* __restrict__ pos_out,        // [K,B,T,T]
    float* __restrict__ neg_out,        // [K,B,T,T]
    float* __restrict__ msk_out,        // [K,B,T,T]
    float* __restrict__ nbr_out)        // [K,B,T,D]
{
    const int kb   = blockIdx.x;        // 0 .. K*B-1
    const int k    = kb >> 12;          // B = 4096
    const int b    = kb & (PB - 1);
    const int tid  = threadIdx.x;       // 0..127
    const int warp = tid >> 5;
    const int lane = tid & 31;

    __shared__ float s_nsim[PT];
    __shared__ int   s_same[PT];
    __shared__ int   s_idx[PT];

    const float* semb_k = semb + (size_t)k * PB * PD;

    // Anchor embedding: each lane holds float4 covering dims [lane*4, lane*4+4)
    const float4 a = reinterpret_cast<const float4*>(semb_k + (size_t)b * PD)[lane];

    const int anchor_label = slabels[k * PB + b];

    if (tid < PT) {
        const int idx = topk[((size_t)kb) * PT + tid];
        s_idx[tid]  = idx;
        s_same[tid] = (slabels[k * PB + idx] == anchor_label) ? 1 : 0;
    }
    __syncthreads();

    // ---- Gather phase: 4 warps x 8 neighbors ----------------------------
    float* nbr_base = nbr_out + (size_t)kb * PT * PD;
    #pragma unroll
    for (int i = 0; i < PT / 4; ++i) {
        const int t = warp + i * 4;
        const float4 v = reinterpret_cast<const float4*>(
                             semb_k + (size_t)s_idx[t] * PD)[lane];
        reinterpret_cast<float4*>(nbr_base + t * PD)[lane] = v;
        float p = v.x * a.x + v.y * a.y + v.z * a.z + v.w * a.w;
        #pragma unroll
        for (int off = 16; off; off >>= 1)
            p += __shfl_xor_sync(0xffffffffu, p, off);
        if (lane == 0) s_nsim[t] = p;
    }
    __syncthreads();

    // ---- Pair phase: 1024 (s,d) pairs per anchor, float4 stores ---------
    // float4 index p in [0,256): s = p/8 (fixed within a float4), d0 = (p%8)*4
    float4* pos4 = reinterpret_cast<float4*>(pos_out + (size_t)kb * PT * PT);
    float4* neg4 = reinterpret_cast<float4*>(neg_out + (size_t)kb * PT * PT);
    float4* msk4 = reinterpret_cast<float4*>(msk_out + (size_t)kb * PT * PT);

    #pragma unroll
    for (int i = 0; i < 2; ++i) {
        const int p  = tid + i * 128;      // 0..255
        const int s  = p >> 3;
        const int d0 = (p & 7) << 2;

        const int   ss = s_same[s];
        const float ns = s_nsim[s];

        const int m0 = ss & (s_same[d0 + 0] ^ 1);
        const int m1 = ss & (s_same[d0 + 1] ^ 1);
        const int m2 = ss & (s_same[d0 + 2] ^ 1);
        const int m3 = ss & (s_same[d0 + 3] ^ 1);

        float4 mv, pv, nv;
        mv.x = (float)m0; mv.y = (float)m1; mv.z = (float)m2; mv.w = (float)m3;
        pv.x = m0 ? ns : 0.0f;
        pv.y = m1 ? ns : 0.0f;
        pv.z = m2 ? ns : 0.0f;
        pv.w = m3 ? ns : 0.0f;
        nv.x = m0 ? s_nsim[d0 + 0] : 0.0f;
        nv.y = m1 ? s_nsim[d0 + 1] : 0.0f;
        nv.z = m2 ? s_nsim[d0 + 2] : 0.0f;
        nv.w = m3 ? s_nsim[d0 + 3] : 0.0f;

        pos4[p] = pv;
        neg4[p] = nv;
        msk4[p] = mv;
    }
}

extern "C" void kernel_launch(void* const* d_in, const int* in_sizes, int n_in,
                              void* d_out, int out_size)
{
    (void)in_sizes; (void)n_in; (void)out_size;

    const float* semb    = (const float*)d_in[0];
    const int*   slabels = (const int*)  d_in[1];
    const int*   topk    = (const int*)  d_in[2];

    float* out = (float*)d_out;
    float* pos = out;
    float* neg = out + PAIR_ELEMS;
    float* msk = out + 2 * PAIR_ELEMS;
    float* nbr = out + 3 * PAIR_ELEMS;

    dim3 grid(PK * PB);   // 16384 CTAs
    dim3 block(128);
    distance_layer_kernel<<<grid, block>>>(semb, slabels, topk,
                                           pos, neg, msk, nbr);
}

// round 5
// speedup vs baseline: 1.0907x; 1.0907x over previous
#include <cuda_runtime.h>
#include <cstdint>

// Problem shape (fixed by the dataset)
#define PK 4
#define PB 4096
#define PT 32
#define PD 128

// Output layout: pos_dist | neg_dist | pair_mask | nbr_embed, all float32,
// flattened in reference-return order.
#define PAIR_ELEMS ((size_t)PK * PB * PT * PT)   // 16,777,216
#define NBR_ELEMS  ((size_t)PK * PB * PT * PD)   // 16,777,216

__global__ __launch_bounds__(128) void distance_layer_kernel(
    const float* __restrict__ semb,     // [K,B,D]
    const int*   __restrict__ slabels,  // [K,B]
    const int*   __restrict__ topk,     // [K,B,T]
    float* __restrict__ pos_out,        // [K,B,T,T]
    float* __restrict__ neg_out,        // [K,B,T,T]
    float* __restrict__ msk_out,        // [K,B,T,T]
    float* __restrict__ nbr_out)        // [K,B,T,D]
{
    const int kb   = blockIdx.x;        // 0 .. K*B-1
    const int k    = kb >> 12;          // B = 4096
    const int b    = kb & (PB - 1);
    const int tid  = threadIdx.x;       // 0..127
    const int warp = tid >> 5;
    const int lane = tid & 31;

    __shared__ float s_nsim[PT];
    __shared__ int   s_same[PT];
    __shared__ int   s_idx[PT];

    const float* semb_k = semb + (size_t)k * PB * PD;

    // Anchor embedding: each lane holds float4 covering dims [lane*4, lane*4+4)
    const float4 a = reinterpret_cast<const float4*>(semb_k + (size_t)b * PD)[lane];

    const int anchor_label = slabels[k * PB + b];

    if (tid < PT) {
        const int idx = topk[((size_t)kb) * PT + tid];
        s_idx[tid]  = idx;
        s_same[tid] = (slabels[k * PB + idx] == anchor_label) ? 1 : 0;
    }
    __syncthreads();

    // ---- Gather phase: 4 warps x 8 neighbors ----------------------------
    // Streaming (evict-first) stores: outputs are never re-read, so give
    // them zero L2 residency. This keeps the 8 MB semb gather table hot in
    // L2 across the whole launch (it's otherwise evicted by 256 MB of
    // write streaming, costing ~160 MB of DRAM re-reads).
    float* nbr_base = nbr_out + (size_t)kb * PT * PD;
    #pragma unroll
    for (int i = 0; i < PT / 4; ++i) {
        const int t = warp + i * 4;
        const float4 v = reinterpret_cast<const float4*>(
                             semb_k + (size_t)s_idx[t] * PD)[lane];
        __stcs(reinterpret_cast<float4*>(nbr_base + t * PD) + lane, v);
        float p = v.x * a.x + v.y * a.y + v.z * a.z + v.w * a.w;
        #pragma unroll
        for (int off = 16; off; off >>= 1)
            p += __shfl_xor_sync(0xffffffffu, p, off);
        if (lane == 0) s_nsim[t] = p;
    }
    __syncthreads();

    // ---- Pair phase: 1024 (s,d) pairs per anchor, float4 stores ---------
    // float4 index p in [0,256): s = p/8 (fixed within a float4), d0 = (p%8)*4
    float4* pos4 = reinterpret_cast<float4*>(pos_out + (size_t)kb * PT * PT);
    float4* neg4 = reinterpret_cast<float4*>(neg_out + (size_t)kb * PT * PT);
    float4* msk4 = reinterpret_cast<float4*>(msk_out + (size_t)kb * PT * PT);

    #pragma unroll
    for (int i = 0; i < 2; ++i) {
        const int p  = tid + i * 128;      // 0..255
        const int s  = p >> 3;
        const int d0 = (p & 7) << 2;

        const int   ss = s_same[s];
        const float ns = s_nsim[s];

        const int m0 = ss & (s_same[d0 + 0] ^ 1);
        const int m1 = ss & (s_same[d0 + 1] ^ 1);
        const int m2 = ss & (s_same[d0 + 2] ^ 1);
        const int m3 = ss & (s_same[d0 + 3] ^ 1);

        float4 mv, pv, nv;
        mv.x = (float)m0; mv.y = (float)m1; mv.z = (float)m2; mv.w = (float)m3;
        pv.x = m0 ? ns : 0.0f;
        pv.y = m1 ? ns : 0.0f;
        pv.z = m2 ? ns : 0.0f;
        pv.w = m3 ? ns : 0.0f;
        nv.x = m0 ? s_nsim[d0 + 0] : 0.0f;
        nv.y = m1 ? s_nsim[d0 + 1] : 0.0f;
        nv.z = m2 ? s_nsim[d0 + 2] : 0.0f;
        nv.w = m3 ? s_nsim[d0 + 3] : 0.0f;

        __stcs(pos4 + p, pv);
        __stcs(neg4 + p, nv);
        __stcs(msk4 + p, mv);
    }
}

extern "C" void kernel_launch(void* const* d_in, const int* in_sizes, int n_in,
                              void* d_out, int out_size)
{
    (void)in_sizes; (void)n_in; (void)out_size;

    const float* semb    = (const float*)d_in[0];
    const int*   slabels = (const int*)  d_in[1];
    const int*   topk    = (const int*)  d_in[2];

    float* out = (float*)d_out;
    float* pos = out;
    float* neg = out + PAIR_ELEMS;
    float* msk = out + 2 * PAIR_ELEMS;
    float* nbr = out + 3 * PAIR_ELEMS;

    dim3 grid(PK * PB);   // 16384 CTAs
    dim3 block(128);
    distance_layer_kernel<<<grid, block>>>(semb, slabels, topk,
                                           pos, neg, msk, nbr);
}

// round 7
// speedup vs baseline: 1.1138x; 1.0212x over previous
#include <cuda_runtime.h>
#include <cstdint>

// Problem shape (fixed by the dataset)
#define PK 4
#define PB 4096
#define PT 32
#define PD 128

#define PAIR_ELEMS ((size_t)PK * PB * PT * PT)   // 16,777,216
#define NBR_ELEMS  ((size_t)PK * PB * PT * PD)   // 16,777,216

// 256-bit L2-policy-qualified accesses (sm_103 ptxas requires .v8.b32 form
// for L2::evict_* modifiers).
__device__ __forceinline__ void ldg8_evict_last(const float* p, float* v) {
    asm volatile("ld.global.nc.L2::evict_last.v8.b32 "
                 "{%0,%1,%2,%3,%4,%5,%6,%7}, [%8];"
                 : "=f"(v[0]), "=f"(v[1]), "=f"(v[2]), "=f"(v[3]),
                   "=f"(v[4]), "=f"(v[5]), "=f"(v[6]), "=f"(v[7])
                 : "l"(p));
}
__device__ __forceinline__ void stg8_evict_first(float* p, const float* v) {
    asm volatile("st.global.L2::evict_first.v8.b32 "
                 "[%0], {%1,%2,%3,%4,%5,%6,%7,%8};"
                 :: "l"(p),
                    "f"(v[0]), "f"(v[1]), "f"(v[2]), "f"(v[3]),
                    "f"(v[4]), "f"(v[5]), "f"(v[6]), "f"(v[7])
                 : "memory");
}

__global__ __launch_bounds__(128) void distance_layer_kernel(
    const float* __restrict__ semb,     // [K,B,D]
    const int*   __restrict__ slabels,  // [K,B]
    const int*   __restrict__ topk,     // [K,B,T]
    float* __restrict__ pos_out,        // [K,B,T,T]
    float* __restrict__ neg_out,        // [K,B,T,T]
    float* __restrict__ msk_out,        // [K,B,T,T]
    float* __restrict__ nbr_out)        // [K,B,T,D]
{
    const int kb   = blockIdx.x;        // 0 .. K*B-1
    const int k    = kb >> 12;          // B = 4096
    const int b    = kb & (PB - 1);
    const int tid  = threadIdx.x;       // 0..127
    const int warp = tid >> 5;
    const int lane = tid & 31;
    const int half = lane >> 4;         // which of 2 rows this half-warp owns
    const int l16  = lane & 15;         // position within the 512B row

    __shared__ float s_nsim[PT];
    __shared__ int   s_same[PT];
    __shared__ int   s_idx[PT];

    const float* semb_k = semb + (size_t)k * PB * PD;

    // Anchor embedding: thread covers dims [l16*8, l16*8+8) (halves replicate)
    float a8[8];
    ldg8_evict_last(semb_k + (size_t)b * PD + l16 * 8, a8);

    const int anchor_label = slabels[k * PB + b];

    if (tid < PT) {
        const int idx = topk[((size_t)kb) * PT + tid];
        s_idx[tid]  = idx;
        s_same[tid] = (slabels[k * PB + idx] == anchor_label) ? 1 : 0;
    }
    __syncthreads();

    // ---- Gather phase: 4 warps x (4 iters x 2 rows) = 32 rows ------------
    // semb rows: L2 evict-last (8 MB table stays resident).
    // Outputs: L2 evict-first (written once, never re-read).
    float* nbr_base = nbr_out + (size_t)kb * PT * PD;
    #pragma unroll
    for (int i = 0; i < 4; ++i) {
        const int t = warp * 8 + i * 2 + half;
        float v[8];
        ldg8_evict_last(semb_k + (size_t)s_idx[t] * PD + l16 * 8, v);
        stg8_evict_first(nbr_base + t * PD + l16 * 8, v);
        float p = v[0]*a8[0] + v[1]*a8[1] + v[2]*a8[2] + v[3]*a8[3]
                + v[4]*a8[4] + v[5]*a8[5] + v[6]*a8[6] + v[7]*a8[7];
        #pragma unroll
        for (int off = 8; off; off >>= 1)
            p += __shfl_xor_sync(0xffffffffu, p, off);
        if (l16 == 0) s_nsim[t] = p;
    }
    __syncthreads();

    // ---- Pair phase: 1024 (s,d) pairs = 128 float8 per tensor ------------
    // tid p covers row s = p>>2, cols d0..d0+7 with d0 = (p&3)*8.
    float* pos_base = pos_out + (size_t)kb * PT * PT;
    float* neg_base = neg_out + (size_t)kb * PT * PT;
    float* msk_base = msk_out + (size_t)kb * PT * PT;

    const int s  = tid >> 2;
    const int d0 = (tid & 3) << 3;

    const int   ss = s_same[s];
    const float ns = s_nsim[s];

    float pv[8], nv[8], mv[8];
    #pragma unroll
    for (int j = 0; j < 8; ++j) {
        const int m = ss & (s_same[d0 + j] ^ 1);
        mv[j] = (float)m;
        pv[j] = m ? ns : 0.0f;
        nv[j] = m ? s_nsim[d0 + j] : 0.0f;
    }

    stg8_evict_first(pos_base + tid * 8, pv);
    stg8_evict_first(neg_base + tid * 8, nv);
    stg8_evict_first(msk_base + tid * 8, mv);
}

extern "C" void kernel_launch(void* const* d_in, const int* in_sizes, int n_in,
                              void* d_out, int out_size)
{
    (void)in_sizes; (void)n_in; (void)out_size;

    const float* semb    = (const float*)d_in[0];
    const int*   slabels = (const int*)  d_in[1];
    const int*   topk    = (const int*)  d_in[2];

    float* out = (float*)d_out;
    float* pos = out;
    float* neg = out + PAIR_ELEMS;
    float* msk = out + 2 * PAIR_ELEMS;
    float* nbr = out + 3 * PAIR_ELEMS;

    dim3 grid(PK * PB);   // 16384 CTAs
    dim3 block(128);
    distance_layer_kernel<<<grid, block>>>(semb, slabels, topk,
                                           pos, neg, msk, nbr);
}